// round 13
// baseline (speedup 1.0000x reference)
#include <cuda_runtime.h>
#include <cuda_fp16.h>
#include <cstdint>
#include <math.h>

typedef __half fp16;

// Problem constants
#define BB 4
#define TT 512
#define DD 1024
#define HH 8
#define DH 64
#define HD 512
#define PP 2048
#define NTOK (BB*TT)          // 2048 tokens

// ================= scratch (device globals) =================================
__device__ fp16  g_xn16[NTOK*DD];
__device__ float g_xt  [NTOK*PP];
__device__ fp16  g_xt16[NTOK*PP];
__device__ float g_xc  [NTOK*PP];
__device__ fp16  g_xc16[NTOK*PP];
__device__ float g_r   [NTOK*HD], g_skip[NTOK*HD];
__device__ float g_q   [NTOK*HD], g_k   [NTOK*HD];
__device__ float g_v   [NTOK*HD], g_o   [NTOK*HD];
__device__ float g_ig  [NTOK*HH], g_fg  [NTOK*HH];
__device__ float g_a   [BB*HH*TT], g_M [BB*HH*TT];
__device__ fp16  g_cm16[NTOK*HD];
// transposed weights (fp16): WT[N,K]
__device__ fp16 g_WlrT[2560*DD];      // [Wl | Wr] cols, K=1024
__device__ fp16 g_WsT[HD*PP], g_WqT[HD*PP], g_WkT[HD*PP];
__device__ fp16 g_WvT[HD*PP], g_WoT[HD*PP], g_WdT[DD*HD];
__device__ float g_bias_lr[2560];

__device__ __forceinline__ uint32_t smem_u32(const void* p) {
    uint32_t a;
    asm("{ .reg .u64 t; cvta.to.shared.u64 t, %1; cvt.u32.u64 %0, t; }"
        : "=r"(a) : "l"(p));
    return a;
}
__device__ __forceinline__ void cp16(uint32_t s, const void* g) {
    asm volatile("cp.async.cg.shared.global [%0], [%1], 16;" :: "r"(s), "l"(g));
}
__device__ __forceinline__ void ldm4(uint32_t addr, uint32_t* r) {
    asm volatile("ldmatrix.sync.aligned.m8n8.x4.shared.b16 {%0,%1,%2,%3}, [%4];"
                 : "=r"(r[0]), "=r"(r[1]), "=r"(r[2]), "=r"(r[3]) : "r"(addr));
}
__device__ __forceinline__ void mma16816(float* c, const uint32_t* a,
                                         uint32_t b0, uint32_t b1) {
    asm volatile("mma.sync.aligned.m16n8k16.row.col.f32.f16.f16.f32 "
        "{%0,%1,%2,%3}, {%4,%5,%6,%7}, {%8,%9}, {%0,%1,%2,%3};"
        : "+f"(c[0]), "+f"(c[1]), "+f"(c[2]), "+f"(c[3])
        : "r"(a[0]), "r"(a[1]), "r"(a[2]), "r"(a[3]), "r"(b0), "r"(b1));
}

// ================= merged weight transpose (fp16) ==========================
struct PrepJobs {
    const float* W[8];
    fp16* T[8];
    int K[8], N[8], cum[9];
};
__global__ __launch_bounds__(256) void prep_all_kernel(PrepJobs pj)
{
    int bx = blockIdx.x, j = 0;
    #pragma unroll
    for (int i = 0; i < 8; i++) if (bx >= pj.cum[i + 1]) j = i + 1;
    const int local = bx - pj.cum[j];
    const int K = pj.K[j], N = pj.N[j];
    const int nbn = N / 32;
    const int n0 = (local % nbn) * 32, k0 = (local / nbn) * 32;
    const float* W = pj.W[j];
    fp16* T = pj.T[j];

    __shared__ float tile[32][33];
    int tx = threadIdx.x & 31, ty = threadIdx.x >> 5;
    for (int r = ty; r < 32; r += 8)
        tile[r][tx] = W[(size_t)(k0 + r) * N + n0 + tx];
    __syncthreads();
    for (int r = ty; r < 32; r += 8)
        T[(size_t)(n0 + r) * K + k0 + tx] = __float2half(tile[tx][r]);
}

__global__ __launch_bounds__(256) void bias_prep_kernel(
    const float* __restrict__ bl, const float* __restrict__ br)
{
    int idx = blockIdx.x * 256 + threadIdx.x;
    if (idx < 2560)
        g_bias_lr[idx] = (idx < PP) ? bl[idx] : br[idx - PP];
}

// ================= layernorm -> fp16 =======================================
__global__ __launch_bounds__(256) void ln_kernel(
    const float* __restrict__ x, const float* __restrict__ w,
    const float* __restrict__ b, fp16* __restrict__ o16)
{
    int t = blockIdx.x;
    const float* row = x + (size_t)t * DD;
    float s = 0.f, s2 = 0.f;
    for (int i = threadIdx.x; i < DD; i += 256) {
        float v = row[i]; s += v; s2 += v * v;
    }
    __shared__ float sh[16];
    int warp = threadIdx.x >> 5, lane = threadIdx.x & 31;
    #pragma unroll
    for (int o = 16; o; o >>= 1) {
        s  += __shfl_xor_sync(0xffffffffu, s,  o);
        s2 += __shfl_xor_sync(0xffffffffu, s2, o);
    }
    if (lane == 0) { sh[warp] = s; sh[8 + warp] = s2; }
    __syncthreads();
    if (threadIdx.x == 0) {
        float ts = 0.f, ts2 = 0.f;
        #pragma unroll
        for (int i = 0; i < 8; i++) { ts += sh[i]; ts2 += sh[8 + i]; }
        float mu  = ts  * (1.f / DD);
        float var = ts2 * (1.f / DD) - mu * mu;
        sh[0] = mu; sh[1] = rsqrtf(var + 1e-6f);
    }
    __syncthreads();
    float mu = sh[0], rstd = sh[1];
    for (int i = threadIdx.x; i < DD; i += 256)
        o16[(size_t)t * DD + i] = __float2half((row[i] - mu) * rstd * w[i] + b[i]);
}

// ============ mma.sync fp16 single-pass GEMM (BK=64, 3-stage) ==============
struct GemmJob {
    const fp16 *A, *B;
    const float *bias, *res;
    float *out;
    fp16 *o16;
    float *out2;                  // columns >= ncut go here (ld = ldo2)
    int ncut, ldo, ldo2;
};
struct GemmParams { GemmJob jobs[5]; int K; };

#define PADK 72                        // halves per smem row (64 + 8 pad)
#define OPT  (128*PADK)                // halves per operand tile
#define STG2 (2*OPT)                   // halves per stage (A, B)
#define GSMEM_BYTES (3*STG2*2)         // 110592 B -> 2 CTAs/SM

__global__ __launch_bounds__(256, 2) void gemm_mma_kernel(GemmParams p)
{
    const GemmJob J = p.jobs[blockIdx.z];
    const int bm = blockIdx.y * 128, bn = blockIdx.x * 128;

    extern __shared__ fp16 smg[];
    const uint32_t sbase = smem_u32(smg);
    const int K = p.K;
    const int tid = threadIdx.x, lane = tid & 31, wid = tid >> 5;
    const int warpM = wid & 3, warpN = wid >> 2;    // 4 x 2 warps, tile 32x64

    const fp16* gsrc[2];
    gsrc[0] = J.A + (size_t)bm * K;
    gsrc[1] = J.B + (size_t)bn * K;

    const int lrow = tid >> 1;
    const int lcol = (tid & 1) * 32;   // halves
    const uint32_t swr = sbase + (uint32_t)(lrow * PADK + lcol) * 2;

    float acc[2][8][4];
    #pragma unroll
    for (int i = 0; i < 2; i++)
        #pragma unroll
        for (int j = 0; j < 8; j++)
            #pragma unroll
            for (int e = 0; e < 4; e++) acc[i][j][e] = 0.f;

    const int NT = K / 64;

    // preload stages 0, 1
    #pragma unroll
    for (int s = 0; s < 2; s++) {
        #pragma unroll
        for (int w = 0; w < 2; w++) {
            const fp16* g = gsrc[w] + (size_t)lrow * K + s * 64 + lcol;
            uint32_t sa = swr + (uint32_t)(s * STG2 + w * OPT) * 2;
            cp16(sa, g); cp16(sa + 16, g + 8); cp16(sa + 32, g + 16); cp16(sa + 48, g + 24);
        }
        asm volatile("cp.async.commit_group;");
    }

    for (int kt = 0; kt < NT; kt++) {
        if (kt < NT - 1) asm volatile("cp.async.wait_group 1;");
        else             asm volatile("cp.async.wait_group 0;");
        __syncthreads();

        // prefetch kt+2 (overlaps with compute below)
        if (kt + 2 < NT) {
            const int s = (kt + 2) % 3;
            const int k0 = (kt + 2) * 64;
            #pragma unroll
            for (int w = 0; w < 2; w++) {
                const fp16* g = gsrc[w] + (size_t)lrow * K + k0 + lcol;
                uint32_t sa = swr + (uint32_t)(s * STG2 + w * OPT) * 2;
                cp16(sa, g); cp16(sa + 16, g + 8); cp16(sa + 32, g + 16); cp16(sa + 48, g + 24);
            }
            asm volatile("cp.async.commit_group;");
        }

        const uint32_t stg = sbase + (uint32_t)((kt % 3) * STG2) * 2;
        #pragma unroll
        for (int ks = 0; ks < 4; ks++) {
            const int koff = ks * 16 + ((lane >> 4) << 3);
            const int rsel = lane & 15;
            uint32_t a[2][4], b[4][4];
            #pragma unroll
            for (int i = 0; i < 2; i++) {
                const int row = warpM * 32 + i * 16 + rsel;
                ldm4(stg + (uint32_t)(row * PADK + koff) * 2, a[i]);
            }
            #pragma unroll
            for (int j = 0; j < 4; j++) {
                const int row = warpN * 64 + j * 16 + rsel;
                ldm4(stg + (uint32_t)(OPT + row * PADK + koff) * 2, b[j]);
            }
            #pragma unroll
            for (int i = 0; i < 2; i++)
                #pragma unroll
                for (int j = 0; j < 8; j++)
                    mma16816(acc[i][j], a[i],
                             b[j >> 1][j & 1], b[j >> 1][(j & 1) + 2]);
        }
    }

    const int er = (lane >> 2);
    const int ec = (lane & 3) * 2;
    #pragma unroll
    for (int i = 0; i < 2; i++) {
        #pragma unroll
        for (int j = 0; j < 8; j++) {
            const int row0 = bm + warpM * 32 + i * 16 + er;
            const int col0 = bn + warpN * 64 + j * 8 + ec;
            #pragma unroll
            for (int e = 0; e < 4; e++) {
                const int row = row0 + (e >> 1) * 8;
                const int col = col0 + (e & 1);
                float v = acc[i][j][e] + J.bias[col];
                if (col >= J.ncut) {
                    J.out2[(size_t)row * J.ldo2 + (col - J.ncut)] = v;
                } else {
                    if (J.res) v += J.res[(size_t)row * J.ldo + col];
                    const size_t idx = (size_t)row * J.ldo + col;
                    J.out[idx] = v;
                    if (J.o16) J.o16[idx] = __float2half(v);
                }
            }
        }
    }
}

// ================= causal feature-conv + silu (smem row) ===================
__global__ __launch_bounds__(256) void conv_silu_kernel(
    const float* __restrict__ xt, const float* __restrict__ cw,
    const float* __restrict__ cbp, float* __restrict__ xc,
    fp16* __restrict__ xc16)
{
    const int t = blockIdx.x;
    __shared__ float row[PP];
    const float4* src = (const float4*)(xt + (size_t)t * PP);
    float4* rs = (float4*)row;
    rs[threadIdx.x]       = src[threadIdx.x];
    rs[threadIdx.x + 256] = src[threadIdx.x + 256];
    __syncthreads();
    const float w0 = cw[0], w1 = cw[1], w2 = cw[2], w3 = cw[3], cb = cbp[0];
    #pragma unroll
    for (int i = 0; i < 2; i++) {
        const int p = (threadIdx.x + 256 * i) * 4;
        float o[4];
        #pragma unroll
        for (int e = 0; e < 4; e++) {
            const int pp = p + e;
            float acc = row[pp] * w3 + cb;
            if (pp >= 1) acc += row[pp - 1] * w2;
            if (pp >= 2) acc += row[pp - 2] * w1;
            if (pp >= 3) acc += row[pp - 3] * w0;
            o[e] = acc / (1.f + __expf(-acc));
        }
        *(float4*)(xc + (size_t)t * PP + p) = make_float4(o[0], o[1], o[2], o[3]);
        __half2* h2 = (__half2*)(xc16 + (size_t)t * PP + p);
        h2[0] = __floats2half2_rn(o[0], o[1]);
        h2[1] = __floats2half2_rn(o[2], o[3]);
    }
}

// ============== i/f gates as tiled fp32 GEMM (exact, M64 x N16) ============
// grid 32 CTAs; thread (tx,ty): tokens {tx, tx+16, tx+32, tx+48}, col ty.
#define GBK 32
__global__ __launch_bounds__(256) void gates_gemm_kernel(
    const float* __restrict__ xc,
    const float* __restrict__ Wi, const float* __restrict__ bi,
    const float* __restrict__ Wf, const float* __restrict__ bf_,
    float* __restrict__ gi, float* __restrict__ gf)
{
    __shared__ float As[GBK][68];   // [k][m] transposed A tile
    __shared__ float Ws[GBK][17];   // [k][n]
    const int tid = threadIdx.x;
    const int tx = tid & 15, ty = tid >> 4;
    const int t0 = blockIdx.x * 64;
    const int lm = tid >> 2;            // 0..63
    const int lk = (tid & 3) * 8;       // 0,8,16,24
    const int ln = tid & 15, lw = tid >> 4;

    float acc[4] = {0.f, 0.f, 0.f, 0.f};

    for (int k0 = 0; k0 < PP; k0 += GBK) {
        #pragma unroll
        for (int c = 0; c < 2; c++) {
            float4 v = *(const float4*)(xc + (size_t)(t0 + lm) * PP + k0 + lk + c * 4);
            As[lk + c*4 + 0][lm] = v.x;
            As[lk + c*4 + 1][lm] = v.y;
            As[lk + c*4 + 2][lm] = v.z;
            As[lk + c*4 + 3][lm] = v.w;
        }
        #pragma unroll
        for (int c = 0; c < 2; c++) {
            const int kk = lw + c * 16;
            Ws[kk][ln] = (ln < 8) ? Wi[(k0 + kk) * HH + ln]
                                  : Wf[(k0 + kk) * HH + (ln - 8)];
        }
        __syncthreads();
        #pragma unroll
        for (int k = 0; k < GBK; k++) {
            const float w = Ws[k][ty];
            acc[0] += As[k][tx +  0] * w;
            acc[1] += As[k][tx + 16] * w;
            acc[2] += As[k][tx + 32] * w;
            acc[3] += As[k][tx + 48] * w;
        }
        __syncthreads();
    }
    const float bias = (ty < 8) ? bi[ty] : bf_[ty - 8];
    float* dst = (ty < 8) ? gi : gf;
    const int h = (ty < 8) ? ty : ty - 8;
    #pragma unroll
    for (int e = 0; e < 4; e++) {
        const int t = t0 + tx + 16 * e;
        dst[t * HH + h] = 15.f * tanhf((acc[e] + bias) * (1.f / 15.f));
    }
}

// ================= gate prefix scans (exact linearization) =================
__global__ __launch_bounds__(TT) void gatescan_kernel(
    const float* __restrict__ gi, const float* __restrict__ gf,
    float* __restrict__ a_out, float* __restrict__ M_out)
{
    const int bh = blockIdx.x;          // b*HH + h
    const int b = bh >> 3, h = bh & 7;
    const int t = threadIdx.x;
    __shared__ float sf[TT], sa[TT];
    const int gidx = (b * TT + t) * HH + h;
    sf[t] = gf[gidx];
    const float iv = gi[gidx];
    __syncthreads();
    #pragma unroll
    for (int st = 1; st < TT; st <<= 1) {
        float add = (t >= st) ? sf[t - st] : 0.f;
        __syncthreads();
        sf[t] += add;
        __syncthreads();
    }
    const float a = iv - sf[t];
    a_out[bh * TT + t] = a;
    sa[t] = a;
    __syncthreads();
    #pragma unroll
    for (int st = 1; st < TT; st <<= 1) {
        float mx = (t >= st) ? sa[t - st] : -3.4e38f;
        __syncthreads();
        sa[t] = fmaxf(sa[t], mx);
        __syncthreads();
    }
    M_out[bh * TT + t] = fmaxf(0.f, sa[t]);
}

// ================= parallel attention-form scan ============================
#define QT 64
#define AP 68                       // row pad (floats); 272B, 16B aligned
#define ASM_BYTES ((4*QT*AP + QT) * 4)

__global__ __launch_bounds__(256) void attn_kernel(
    const float* __restrict__ q, const float* __restrict__ kraw,
    const float* __restrict__ v, const float* __restrict__ aex,
    const float* __restrict__ Mex, const float* __restrict__ oraw,
    const float* __restrict__ skip, const float* __restrict__ rraw,
    const float* __restrict__ hlnw, const float* __restrict__ hlnb,
    fp16* __restrict__ out16)
{
    const int bh = blockIdx.y, b = bh >> 3, h = bh & 7;
    const int t0 = blockIdx.x * QT;
    extern __shared__ float sm[];
    float* ks = sm;                  // [64][AP]
    float* vs = ks + QT * AP;
    float* qs = vs + QT * AP;
    float* ss = qs + QT * AP;
    float* as_ = ss + QT * AP;       // [64]

    const int tid = threadIdx.x;
    const int qi = tid >> 2, sub = tid & 3;
    const int tq = t0 + qi;
    const size_t qbase = (size_t)(b * TT + tq) * HD + h * DH;

    {
        const int lr = tid >> 2, lc = (tid & 3) * 16;
        const float* src = q + (size_t)(b * TT + t0 + lr) * HD + h * DH + lc;
        #pragma unroll
        for (int i = 0; i < 16; i += 4)
            *(float4*)&qs[lr * AP + lc + i] = *(const float4*)(src + i);
    }
    __syncthreads();

    const float Mt = Mex[bh * TT + tq];
    float num[16];
    #pragma unroll
    for (int i = 0; i < 16; i++) num[i] = 0.f;
    float den = 0.f;

    for (int j0 = 0; j0 <= t0; j0 += QT) {
        {
            const int lr = tid >> 2, lc = (tid & 3) * 16;
            const size_t gb = (size_t)(b * TT + j0 + lr) * HD + h * DH + lc;
            #pragma unroll
            for (int i = 0; i < 16; i += 4) {
                *(float4*)&ks[lr * AP + lc + i] = *(const float4*)(kraw + gb + i);
                *(float4*)&vs[lr * AP + lc + i] = *(const float4*)(v + gb + i);
            }
            if (tid < QT) as_[tid] = aex[bh * TT + j0 + tid];
        }
        __syncthreads();

        float sc[16];
        #pragma unroll
        for (int jj = 0; jj < 16; jj++) sc[jj] = 0.f;
        const float* qrow = &qs[qi * AP];
        #pragma unroll 4
        for (int d = 0; d < DH; d += 4) {
            float q0 = qrow[d], q1 = qrow[d+1], q2 = qrow[d+2], q3 = qrow[d+3];
            #pragma unroll
            for (int jj = 0; jj < 16; jj++) {
                const float* kr = &ks[(sub + 4*jj) * AP + d];
                sc[jj] += q0*kr[0] + q1*kr[1] + q2*kr[2] + q3*kr[3];
            }
        }
        const bool diag = (j0 == t0);
        #pragma unroll
        for (int jj = 0; jj < 16; jj++) {
            const int j = sub + 4*jj;
            float w = (diag && j > qi) ? 0.f
                      : __expf(as_[j] - Mt) * 0.125f * sc[jj];
            ss[qi * AP + j] = w;
            den += w;
        }
        __syncthreads();

        #pragma unroll 8
        for (int j = 0; j < QT; j++) {
            const float s = ss[qi * AP + j];
            const float* vr = &vs[j * AP + sub];
            #pragma unroll
            for (int dd = 0; dd < 16; dd++)
                num[dd] += s * vr[4*dd];
        }
        __syncthreads();
    }

    float sumq = 0.f;
    #pragma unroll
    for (int dd = 0; dd < 16; dd++) sumq += qs[qi * AP + sub + 4*dd];
    den  += __shfl_xor_sync(0xffffffffu, den, 1);
    den  += __shfl_xor_sync(0xffffffffu, den, 2);
    sumq += __shfl_xor_sync(0xffffffffu, sumq, 1);
    sumq += __shfl_xor_sync(0xffffffffu, sumq, 2);
    den = fmaxf(den + __expf(-Mt) * sumq, 1.0f);
    const float rden = 1.f / den;

    float hh[16], s1 = 0.f, s2 = 0.f;
    #pragma unroll
    for (int dd = 0; dd < 16; dd++) {
        const int d = sub + 4*dd;
        const float ov = oraw[qbase + d];
        const float og = 1.f / (1.f + __expf(-ov));
        const float hv = og * num[dd] * rden;
        hh[dd] = hv;
        s1 += hv; s2 += hv * hv;
    }
    s1 += __shfl_xor_sync(0xffffffffu, s1, 1);
    s1 += __shfl_xor_sync(0xffffffffu, s1, 2);
    s2 += __shfl_xor_sync(0xffffffffu, s2, 1);
    s2 += __shfl_xor_sync(0xffffffffu, s2, 2);
    const float mu  = s1 * (1.f / DH);
    const float var = s2 * (1.f / DH) - mu * mu;
    const float rstd = rsqrtf(var + 1e-6f);
    #pragma unroll
    for (int dd = 0; dd < 16; dd++) {
        const int d = sub + 4*dd;
        const float hn = (hh[dd] - mu) * rstd * hlnw[h*DH + d] + hlnb[h*DH + d];
        const float rv = rraw[qbase + d];
        const float sil = rv / (1.f + __expf(-rv));
        out16[qbase + d] = __float2half((hn + skip[qbase + d]) * sil);
    }
}

// ===========================================================================
extern "C" void kernel_launch(void* const* d_in, const int* in_sizes, int n_in,
                              void* d_out, int out_size)
{
    const float* x      = (const float*)d_in[0];
    const float* ln_w   = (const float*)d_in[1];
    const float* ln_b   = (const float*)d_in[2];
    const float* hln_w  = (const float*)d_in[3];
    const float* hln_b  = (const float*)d_in[4];
    const float* Wl     = (const float*)d_in[5];
    const float* bl     = (const float*)d_in[6];
    const float* Wr     = (const float*)d_in[7];
    const float* br     = (const float*)d_in[8];
    const float* conv_w = (const float*)d_in[9];
    const float* conv_b = (const float*)d_in[10];
    const float* Wskip  = (const float*)d_in[11];
    const float* bskip  = (const float*)d_in[12];
    const float* Wi     = (const float*)d_in[13];
    const float* bi     = (const float*)d_in[14];
    const float* Wf     = (const float*)d_in[15];
    const float* bf_    = (const float*)d_in[16];
    const float* Wo     = (const float*)d_in[17];
    const float* bo     = (const float*)d_in[18];
    const float* Wq     = (const float*)d_in[19];
    const float* bq     = (const float*)d_in[20];
    const float* Wk     = (const float*)d_in[21];
    const float* bk     = (const float*)d_in[22];
    const float* Wv     = (const float*)d_in[23];
    const float* bv     = (const float*)d_in[24];
    const float* Wd     = (const float*)d_in[25];
    const float* bd     = (const float*)d_in[26];
    float* out = (float*)d_out;

    fp16 *xn16, *xt16, *xc16, *cm16;
    fp16 *WlrT, *WsT, *WqT, *WkT, *WvT, *WoT, *WdT;
    float *xt, *xc, *r, *skip, *q, *k, *v, *o, *gi, *gf, *aex, *Mex, *bias_lr;
    cudaGetSymbolAddress((void**)&xn16, g_xn16);
    cudaGetSymbolAddress((void**)&xt,   g_xt);   cudaGetSymbolAddress((void**)&xt16, g_xt16);
    cudaGetSymbolAddress((void**)&xc,   g_xc);   cudaGetSymbolAddress((void**)&xc16, g_xc16);
    cudaGetSymbolAddress((void**)&r,    g_r);    cudaGetSymbolAddress((void**)&skip, g_skip);
    cudaGetSymbolAddress((void**)&q,    g_q);    cudaGetSymbolAddress((void**)&k,    g_k);
    cudaGetSymbolAddress((void**)&v,    g_v);    cudaGetSymbolAddress((void**)&o,    g_o);
    cudaGetSymbolAddress((void**)&gi,   g_ig);   cudaGetSymbolAddress((void**)&gf,   g_fg);
    cudaGetSymbolAddress((void**)&aex,  g_a);    cudaGetSymbolAddress((void**)&Mex,  g_M);
    cudaGetSymbolAddress((void**)&cm16, g_cm16);
    cudaGetSymbolAddress((void**)&WlrT, g_WlrT);
    cudaGetSymbolAddress((void**)&WsT,  g_WsT);  cudaGetSymbolAddress((void**)&WqT,  g_WqT);
    cudaGetSymbolAddress((void**)&WkT,  g_WkT);  cudaGetSymbolAddress((void**)&WvT,  g_WvT);
    cudaGetSymbolAddress((void**)&WoT,  g_WoT);  cudaGetSymbolAddress((void**)&WdT,  g_WdT);
    cudaGetSymbolAddress((void**)&bias_lr, g_bias_lr);

    cudaFuncSetAttribute(gemm_mma_kernel,
                         cudaFuncAttributeMaxDynamicSharedMemorySize, GSMEM_BYTES);
    cudaFuncSetAttribute(attn_kernel,
                         cudaFuncAttributeMaxDynamicSharedMemorySize, ASM_BYTES);

    // 1. merged weight prep (8 transpose jobs in one launch)
    {
        PrepJobs pj{};
        const float* Ws[8] = { Wl, Wr, Wskip, Wq, Wk, Wv, Wo, Wd };
        fp16* Ts[8] = { WlrT, WlrT + (size_t)PP * DD, WsT, WqT, WkT, WvT, WoT, WdT };
        int Ks[8] = { DD, DD, PP, PP, PP, PP, PP, HD };
        int Ns[8] = { PP, HD, HD, HD, HD, HD, HD, DD };
        int cum = 0;
        for (int i = 0; i < 8; i++) {
            pj.W[i] = Ws[i]; pj.T[i] = Ts[i];
            pj.K[i] = Ks[i]; pj.N[i] = Ns[i];
            pj.cum[i] = cum;
            cum += (Ns[i] / 32) * (Ks[i] / 32);
        }
        pj.cum[8] = cum;
        prep_all_kernel<<<cum, 256>>>(pj);
    }
    bias_prep_kernel<<<10, 256>>>(bl, br);

    // 2. layernorm -> xn fp16
    ln_kernel<<<NTOK, 256>>>(x, ln_w, ln_b, xn16);

    // 3. merged [xt | r] = xn @ [Wl | Wr] + [bl | br]
    {
        GemmParams p{}; p.K = DD;
        p.jobs[0] = { xn16, WlrT, bias_lr, nullptr, xt, xt16, r, PP, PP, HD };
        gemm_mma_kernel<<<dim3(2560/128, NTOK/128, 1), 256, GSMEM_BYTES>>>(p);
    }
    // 4. conv + silu -> xc
    conv_silu_kernel<<<NTOK, 256>>>(xt, conv_w, conv_b, xc, xc16);

    // 5. five P->HD projections in one batched launch
    {
        const int NC = 1 << 30;
        GemmParams p{}; p.K = PP;
        p.jobs[0] = { xc16, WsT, bskip, nullptr, skip, nullptr, nullptr, NC, HD, 0 };
        p.jobs[1] = { xc16, WqT, bq,    nullptr, q,    nullptr, nullptr, NC, HD, 0 };
        p.jobs[2] = { xc16, WkT, bk,    nullptr, k,    nullptr, nullptr, NC, HD, 0 };
        p.jobs[3] = { xt16, WvT, bv,    nullptr, v,    nullptr, nullptr, NC, HD, 0 };
        p.jobs[4] = { xt16, WoT, bo,    nullptr, o,    nullptr, nullptr, NC, HD, 0 };
        gemm_mma_kernel<<<dim3(HD/128, NTOK/128, 5), 256, GSMEM_BYTES>>>(p);
    }
    // 6. i/f gates (fp32 tiled GEMM) + prefix scans
    gates_gemm_kernel<<<NTOK/64, 256>>>(xc, Wi, bi, Wf, bf_, gi, gf);
    gatescan_kernel<<<BB*HH, TT>>>(gi, gf, aex, Mex);

    // 7. parallel attention-form scan -> comb fp16
    attn_kernel<<<dim3(TT/QT, BB*HH), 256, ASM_BYTES>>>(
        q, k, v, aex, Mex, o, skip, r, hln_w, hln_b, cm16);

    // 8. out = comb @ Wd + bd + x
    {
        const int NC = 1 << 30;
        GemmParams p{}; p.K = HD;
        p.jobs[0] = { cm16, WdT, bd, x, out, nullptr, nullptr, NC, DD, 0 };
        gemm_mma_kernel<<<dim3(DD/128, NTOK/128, 1), 256, GSMEM_BYTES>>>(p);
    }
}

// round 14
// speedup vs baseline: 1.2009x; 1.2009x over previous
#include <cuda_runtime.h>
#include <cuda_fp16.h>
#include <cstdint>
#include <math.h>

typedef __half fp16;

// Problem constants
#define BB 4
#define TT 512
#define DD 1024
#define HH 8
#define DH 64
#define HD 512
#define PP 2048
#define NTOK (BB*TT)          // 2048 tokens

// ================= scratch (device globals) =================================
__device__ fp16  g_xn16[NTOK*DD];
__device__ float g_xt  [NTOK*PP];
__device__ fp16  g_xt16[NTOK*PP];
__device__ float g_xc  [NTOK*PP];
__device__ fp16  g_xc16[NTOK*PP];
__device__ float g_r   [NTOK*HD], g_skip[NTOK*HD];
__device__ float g_q   [NTOK*HD], g_k   [NTOK*HD];
__device__ float g_v   [NTOK*HD], g_o   [NTOK*HD];
__device__ float g_ig  [NTOK*HH], g_fg  [NTOK*HH];
__device__ float g_a   [BB*HH*TT], g_M [BB*HH*TT];
__device__ fp16  g_cm16[NTOK*HD];
// transposed weights (fp16): WT[N,K]
__device__ fp16 g_WlrT[2560*DD];      // [Wl | Wr] cols, K=1024
__device__ fp16 g_WsT[HD*PP], g_WqT[HD*PP], g_WkT[HD*PP];
__device__ fp16 g_WvT[HD*PP], g_WoT[HD*PP], g_WdT[DD*HD];
__device__ float g_bias_lr[2560];
__device__ float g_WiT[HH*PP], g_WfT[HH*PP];   // gate weights transposed [H][P]

__device__ __forceinline__ uint32_t smem_u32(const void* p) {
    uint32_t a;
    asm("{ .reg .u64 t; cvta.to.shared.u64 t, %1; cvt.u32.u64 %0, t; }"
        : "=r"(a) : "l"(p));
    return a;
}
__device__ __forceinline__ void cp16(uint32_t s, const void* g) {
    asm volatile("cp.async.cg.shared.global [%0], [%1], 16;" :: "r"(s), "l"(g));
}
__device__ __forceinline__ void ldm4(uint32_t addr, uint32_t* r) {
    asm volatile("ldmatrix.sync.aligned.m8n8.x4.shared.b16 {%0,%1,%2,%3}, [%4];"
                 : "=r"(r[0]), "=r"(r[1]), "=r"(r[2]), "=r"(r[3]) : "r"(addr));
}
__device__ __forceinline__ void mma16816(float* c, const uint32_t* a,
                                         uint32_t b0, uint32_t b1) {
    asm volatile("mma.sync.aligned.m16n8k16.row.col.f32.f16.f16.f32 "
        "{%0,%1,%2,%3}, {%4,%5,%6,%7}, {%8,%9}, {%0,%1,%2,%3};"
        : "+f"(c[0]), "+f"(c[1]), "+f"(c[2]), "+f"(c[3])
        : "r"(a[0]), "r"(a[1]), "r"(a[2]), "r"(a[3]), "r"(b0), "r"(b1));
}

// ================= merged weight transpose (fp16) ==========================
struct PrepJobs {
    const float* W[8];
    fp16* T[8];
    int K[8], N[8], cum[9];
};
__global__ __launch_bounds__(256) void prep_all_kernel(PrepJobs pj)
{
    int bx = blockIdx.x, j = 0;
    #pragma unroll
    for (int i = 0; i < 8; i++) if (bx >= pj.cum[i + 1]) j = i + 1;
    const int local = bx - pj.cum[j];
    const int K = pj.K[j], N = pj.N[j];
    const int nbn = N / 32;
    const int n0 = (local % nbn) * 32, k0 = (local / nbn) * 32;
    const float* W = pj.W[j];
    fp16* T = pj.T[j];

    __shared__ float tile[32][33];
    int tx = threadIdx.x & 31, ty = threadIdx.x >> 5;
    for (int r = ty; r < 32; r += 8)
        tile[r][tx] = W[(size_t)(k0 + r) * N + n0 + tx];
    __syncthreads();
    for (int r = ty; r < 32; r += 8)
        T[(size_t)(n0 + r) * K + k0 + tx] = __float2half(tile[tx][r]);
}

// biases + gate weight transpose (Wi/Wf [P,8] -> [8][P] fp32)
__global__ __launch_bounds__(256) void misc_prep_kernel(
    const float* __restrict__ bl, const float* __restrict__ br,
    const float* __restrict__ Wi, const float* __restrict__ Wf)
{
    const int blk = blockIdx.x, tid = threadIdx.x;
    if (blk < 10) {
        int idx = blk * 256 + tid;
        if (idx < 2560)
            g_bias_lr[idx] = (idx < PP) ? bl[idx] : br[idx - PP];
    } else {
        int idx = (blk - 10) * 256 + tid;   // 0..16383 over [8][2048]
        int h = idx >> 11, p = idx & 2047;
        g_WiT[idx] = Wi[p * HH + h];
        g_WfT[idx] = Wf[p * HH + h];
    }
}

// ================= layernorm -> fp16 =======================================
__global__ __launch_bounds__(256) void ln_kernel(
    const float* __restrict__ x, const float* __restrict__ w,
    const float* __restrict__ b, fp16* __restrict__ o16)
{
    int t = blockIdx.x;
    const float* row = x + (size_t)t * DD;
    float s = 0.f, s2 = 0.f;
    for (int i = threadIdx.x; i < DD; i += 256) {
        float v = row[i]; s += v; s2 += v * v;
    }
    __shared__ float sh[16];
    int warp = threadIdx.x >> 5, lane = threadIdx.x & 31;
    #pragma unroll
    for (int o = 16; o; o >>= 1) {
        s  += __shfl_xor_sync(0xffffffffu, s,  o);
        s2 += __shfl_xor_sync(0xffffffffu, s2, o);
    }
    if (lane == 0) { sh[warp] = s; sh[8 + warp] = s2; }
    __syncthreads();
    if (threadIdx.x == 0) {
        float ts = 0.f, ts2 = 0.f;
        #pragma unroll
        for (int i = 0; i < 8; i++) { ts += sh[i]; ts2 += sh[8 + i]; }
        float mu  = ts  * (1.f / DD);
        float var = ts2 * (1.f / DD) - mu * mu;
        sh[0] = mu; sh[1] = rsqrtf(var + 1e-6f);
    }
    __syncthreads();
    float mu = sh[0], rstd = sh[1];
    for (int i = threadIdx.x; i < DD; i += 256)
        o16[(size_t)t * DD + i] = __float2half((row[i] - mu) * rstd * w[i] + b[i]);
}

// ============ mma.sync fp16 single-pass GEMM (BK=32, 4-stage) ==============
struct GemmJob {
    const fp16 *A, *B;
    const float *bias, *res;
    float *out;
    fp16 *o16;
    float *out2;                  // columns >= ncut go here (ld = ldo2)
    int ncut, ldo, ldo2;
};
struct GemmParams { GemmJob jobs[5]; int K; };

#define PADK 40                        // halves per smem row (32 + 8 pad)
#define OPT  (128*PADK)                // halves per operand tile
#define STG2 (2*OPT)                   // halves per stage (A, B)
#define NSTG 4
#define GSMEM_BYTES (NSTG*STG2*2)      // 81920 B -> 2 CTAs/SM

__global__ __launch_bounds__(256, 2) void gemm_mma_kernel(GemmParams p)
{
    const GemmJob J = p.jobs[blockIdx.z];
    const int bm = blockIdx.y * 128, bn = blockIdx.x * 128;

    extern __shared__ fp16 smg[];
    const uint32_t sbase = smem_u32(smg);
    const int K = p.K;
    const int tid = threadIdx.x, lane = tid & 31, wid = tid >> 5;
    const int warpM = wid & 3, warpN = wid >> 2;    // 4 x 2 warps, tile 32x64

    const fp16* gsrc[2];
    gsrc[0] = J.A + (size_t)bm * K;
    gsrc[1] = J.B + (size_t)bn * K;

    const int lrow = tid >> 1;
    const int lcol = (tid & 1) * 16;   // halves
    const uint32_t swr = sbase + (uint32_t)(lrow * PADK + lcol) * 2;

    float acc[2][8][4];
    #pragma unroll
    for (int i = 0; i < 2; i++)
        #pragma unroll
        for (int j = 0; j < 8; j++)
            #pragma unroll
            for (int e = 0; e < 4; e++) acc[i][j][e] = 0.f;

    const int NT = K / 32;

    // preload stages 0..2
    #pragma unroll
    for (int s = 0; s < 3; s++) {
        #pragma unroll
        for (int w = 0; w < 2; w++) {
            const fp16* g = gsrc[w] + (size_t)lrow * K + s * 32 + lcol;
            uint32_t sa = swr + (uint32_t)(s * STG2 + w * OPT) * 2;
            cp16(sa, g); cp16(sa + 16, g + 8);
        }
        asm volatile("cp.async.commit_group;");
    }

    for (int kt = 0; kt < NT; kt++) {
        if (kt < NT - 2)      asm volatile("cp.async.wait_group 2;");
        else if (kt < NT - 1) asm volatile("cp.async.wait_group 1;");
        else                  asm volatile("cp.async.wait_group 0;");
        __syncthreads();

        // prefetch kt+3 (overlaps with compute below)
        if (kt + 3 < NT) {
            const int s = (kt + 3) % NSTG;
            const int k0 = (kt + 3) * 32;
            #pragma unroll
            for (int w = 0; w < 2; w++) {
                const fp16* g = gsrc[w] + (size_t)lrow * K + k0 + lcol;
                uint32_t sa = swr + (uint32_t)(s * STG2 + w * OPT) * 2;
                cp16(sa, g); cp16(sa + 16, g + 8);
            }
            asm volatile("cp.async.commit_group;");
        }

        const uint32_t stg = sbase + (uint32_t)((kt % NSTG) * STG2) * 2;
        #pragma unroll
        for (int ks = 0; ks < 2; ks++) {
            const int koff = ks * 16 + ((lane >> 4) << 3);
            const int rsel = lane & 15;
            uint32_t a[2][4], b[4][4];
            #pragma unroll
            for (int i = 0; i < 2; i++) {
                const int row = warpM * 32 + i * 16 + rsel;
                ldm4(stg + (uint32_t)(row * PADK + koff) * 2, a[i]);
            }
            #pragma unroll
            for (int j = 0; j < 4; j++) {
                const int row = warpN * 64 + j * 16 + rsel;
                ldm4(stg + (uint32_t)(OPT + row * PADK + koff) * 2, b[j]);
            }
            #pragma unroll
            for (int i = 0; i < 2; i++)
                #pragma unroll
                for (int j = 0; j < 8; j++)
                    mma16816(acc[i][j], a[i],
                             b[j >> 1][j & 1], b[j >> 1][(j & 1) + 2]);
        }
    }

    const int er = (lane >> 2);
    const int ec = (lane & 3) * 2;
    #pragma unroll
    for (int i = 0; i < 2; i++) {
        #pragma unroll
        for (int j = 0; j < 8; j++) {
            const int row0 = bm + warpM * 32 + i * 16 + er;
            const int col0 = bn + warpN * 64 + j * 8 + ec;
            #pragma unroll
            for (int e = 0; e < 4; e++) {
                const int row = row0 + (e >> 1) * 8;
                const int col = col0 + (e & 1);
                float v = acc[i][j][e] + J.bias[col];
                if (col >= J.ncut) {
                    J.out2[(size_t)row * J.ldo2 + (col - J.ncut)] = v;
                } else {
                    if (J.res) v += J.res[(size_t)row * J.ldo + col];
                    const size_t idx = (size_t)row * J.ldo + col;
                    J.out[idx] = v;
                    if (J.o16) J.o16[idx] = __float2half(v);
                }
            }
        }
    }
}

// ================= causal feature-conv + silu ==============================
__global__ __launch_bounds__(256) void conv_silu_kernel(
    const float* __restrict__ xt, const float* __restrict__ cw,
    const float* __restrict__ cbp, float* __restrict__ xc,
    fp16* __restrict__ xc16)
{
    int t = blockIdx.x;
    int pcol = blockIdx.y * 256 + threadIdx.x;
    const float* row = xt + (size_t)t * PP;
    float w0 = cw[0], w1 = cw[1], w2 = cw[2], w3 = cw[3];
    float acc = row[pcol] * w3;
    if (pcol >= 1) acc += row[pcol - 1] * w2;
    if (pcol >= 2) acc += row[pcol - 2] * w1;
    if (pcol >= 3) acc += row[pcol - 3] * w0;
    acc += cbp[0];
    float y = acc / (1.f + expf(-acc));
    size_t idx = (size_t)t * PP + pcol;
    xc[idx] = y;
    xc16[idx] = __float2half(y);
}

// ================= i/f gates (fp32, coalesced transposed weights) ==========
__global__ __launch_bounds__(256) void gates_kernel(
    const float* __restrict__ xc,
    const float* __restrict__ WiT, const float* __restrict__ bi,
    const float* __restrict__ WfT, const float* __restrict__ bf_,
    float* __restrict__ gi, float* __restrict__ gf)
{
    int t = blockIdx.x;
    int warp = threadIdx.x >> 5, lane = threadIdx.x & 31;
    const float* row = xc + (size_t)t * PP;
    const float* wi = WiT + warp * PP;
    const float* wf = WfT + warp * PP;
    float si = 0.f, sf = 0.f;
    for (int p = lane * 4; p < PP; p += 128) {
        float4 xv = *(const float4*)(row + p);
        float4 a  = *(const float4*)(wi + p);
        float4 b  = *(const float4*)(wf + p);
        si += xv.x*a.x + xv.y*a.y + xv.z*a.z + xv.w*a.w;
        sf += xv.x*b.x + xv.y*b.y + xv.z*b.z + xv.w*b.w;
    }
    #pragma unroll
    for (int o = 16; o; o >>= 1) {
        si += __shfl_xor_sync(0xffffffffu, si, o);
        sf += __shfl_xor_sync(0xffffffffu, sf, o);
    }
    if (lane == 0) {
        float a  = si + bi[warp];
        float b2 = sf + bf_[warp];
        gi[t * HH + warp] = 15.f * tanhf(a  * (1.f / 15.f));
        gf[t * HH + warp] = 15.f * tanhf(b2 * (1.f / 15.f));
    }
}

// ================= gate prefix scans (exact linearization) =================
__global__ __launch_bounds__(TT) void gatescan_kernel(
    const float* __restrict__ gi, const float* __restrict__ gf,
    float* __restrict__ a_out, float* __restrict__ M_out)
{
    const int bh = blockIdx.x;          // b*HH + h
    const int b = bh >> 3, h = bh & 7;
    const int t = threadIdx.x;
    __shared__ float sf[TT], sa[TT];
    const int gidx = (b * TT + t) * HH + h;
    sf[t] = gf[gidx];
    const float iv = gi[gidx];
    __syncthreads();
    #pragma unroll
    for (int st = 1; st < TT; st <<= 1) {
        float add = (t >= st) ? sf[t - st] : 0.f;
        __syncthreads();
        sf[t] += add;
        __syncthreads();
    }
    const float a = iv - sf[t];
    a_out[bh * TT + t] = a;
    sa[t] = a;
    __syncthreads();
    #pragma unroll
    for (int st = 1; st < TT; st <<= 1) {
        float mx = (t >= st) ? sa[t - st] : -3.4e38f;
        __syncthreads();
        sa[t] = fmaxf(sa[t], mx);
        __syncthreads();
    }
    M_out[bh * TT + t] = fmaxf(0.f, sa[t]);
}

// ================= parallel attention-form scan ============================
#define QT 64
#define AP 68                       // row pad (floats); 272B, 16B aligned
#define ASM_BYTES ((4*QT*AP + QT) * 4)

__global__ __launch_bounds__(256) void attn_kernel(
    const float* __restrict__ q, const float* __restrict__ kraw,
    const float* __restrict__ v, const float* __restrict__ aex,
    const float* __restrict__ Mex, const float* __restrict__ oraw,
    const float* __restrict__ skip, const float* __restrict__ rraw,
    const float* __restrict__ hlnw, const float* __restrict__ hlnb,
    fp16* __restrict__ out16)
{
    const int bh = blockIdx.y, b = bh >> 3, h = bh & 7;
    const int t0 = blockIdx.x * QT;
    extern __shared__ float sm[];
    float* ks = sm;                  // [64][AP]
    float* vs = ks + QT * AP;
    float* qs = vs + QT * AP;
    float* ss = qs + QT * AP;
    float* as_ = ss + QT * AP;       // [64]

    const int tid = threadIdx.x;
    const int qi = tid >> 2, sub = tid & 3;
    const int tq = t0 + qi;
    const size_t qbase = (size_t)(b * TT + tq) * HD + h * DH;

    {
        const int lr = tid >> 2, lc = (tid & 3) * 16;
        const float* src = q + (size_t)(b * TT + t0 + lr) * HD + h * DH + lc;
        #pragma unroll
        for (int i = 0; i < 16; i += 4)
            *(float4*)&qs[lr * AP + lc + i] = *(const float4*)(src + i);
    }
    __syncthreads();

    const float Mt = Mex[bh * TT + tq];
    float num[16];
    #pragma unroll
    for (int i = 0; i < 16; i++) num[i] = 0.f;
    float den = 0.f;

    for (int j0 = 0; j0 <= t0; j0 += QT) {
        {
            const int lr = tid >> 2, lc = (tid & 3) * 16;
            const size_t gb = (size_t)(b * TT + j0 + lr) * HD + h * DH + lc;
            #pragma unroll
            for (int i = 0; i < 16; i += 4) {
                *(float4*)&ks[lr * AP + lc + i] = *(const float4*)(kraw + gb + i);
                *(float4*)&vs[lr * AP + lc + i] = *(const float4*)(v + gb + i);
            }
            if (tid < QT) as_[tid] = aex[bh * TT + j0 + tid];
        }
        __syncthreads();

        float sc[16];
        #pragma unroll
        for (int jj = 0; jj < 16; jj++) sc[jj] = 0.f;
        const float* qrow = &qs[qi * AP];
        #pragma unroll 4
        for (int d = 0; d < DH; d += 4) {
            float q0 = qrow[d], q1 = qrow[d+1], q2 = qrow[d+2], q3 = qrow[d+3];
            #pragma unroll
            for (int jj = 0; jj < 16; jj++) {
                const float* kr = &ks[(sub + 4*jj) * AP + d];
                sc[jj] += q0*kr[0] + q1*kr[1] + q2*kr[2] + q3*kr[3];
            }
        }
        const bool diag = (j0 == t0);
        #pragma unroll
        for (int jj = 0; jj < 16; jj++) {
            const int j = sub + 4*jj;
            float w = (diag && j > qi) ? 0.f
                      : __expf(as_[j] - Mt) * 0.125f * sc[jj];
            ss[qi * AP + j] = w;
            den += w;
        }
        __syncthreads();

        #pragma unroll 8
        for (int j = 0; j < QT; j++) {
            const float s = ss[qi * AP + j];
            const float* vr = &vs[j * AP + sub];
            #pragma unroll
            for (int dd = 0; dd < 16; dd++)
                num[dd] += s * vr[4*dd];
        }
        __syncthreads();
    }

    float sumq = 0.f;
    #pragma unroll
    for (int dd = 0; dd < 16; dd++) sumq += qs[qi * AP + sub + 4*dd];
    den  += __shfl_xor_sync(0xffffffffu, den, 1);
    den  += __shfl_xor_sync(0xffffffffu, den, 2);
    sumq += __shfl_xor_sync(0xffffffffu, sumq, 1);
    sumq += __shfl_xor_sync(0xffffffffu, sumq, 2);
    den = fmaxf(den + __expf(-Mt) * sumq, 1.0f);
    const float rden = 1.f / den;

    float hh[16], s1 = 0.f, s2 = 0.f;
    #pragma unroll
    for (int dd = 0; dd < 16; dd++) {
        const int d = sub + 4*dd;
        const float ov = oraw[qbase + d];
        const float og = 1.f / (1.f + __expf(-ov));
        const float hv = og * num[dd] * rden;
        hh[dd] = hv;
        s1 += hv; s2 += hv * hv;
    }
    s1 += __shfl_xor_sync(0xffffffffu, s1, 1);
    s1 += __shfl_xor_sync(0xffffffffu, s1, 2);
    s2 += __shfl_xor_sync(0xffffffffu, s2, 1);
    s2 += __shfl_xor_sync(0xffffffffu, s2, 2);
    const float mu  = s1 * (1.f / DH);
    const float var = s2 * (1.f / DH) - mu * mu;
    const float rstd = rsqrtf(var + 1e-6f);
    #pragma unroll
    for (int dd = 0; dd < 16; dd++) {
        const int d = sub + 4*dd;
        const float hn = (hh[dd] - mu) * rstd * hlnw[h*DH + d] + hlnb[h*DH + d];
        const float rv = rraw[qbase + d];
        const float sil = rv / (1.f + __expf(-rv));
        out16[qbase + d] = __float2half((hn + skip[qbase + d]) * sil);
    }
}

// ===========================================================================
extern "C" void kernel_launch(void* const* d_in, const int* in_sizes, int n_in,
                              void* d_out, int out_size)
{
    const float* x      = (const float*)d_in[0];
    const float* ln_w   = (const float*)d_in[1];
    const float* ln_b   = (const float*)d_in[2];
    const float* hln_w  = (const float*)d_in[3];
    const float* hln_b  = (const float*)d_in[4];
    const float* Wl     = (const float*)d_in[5];
    const float* bl     = (const float*)d_in[6];
    const float* Wr     = (const float*)d_in[7];
    const float* br     = (const float*)d_in[8];
    const float* conv_w = (const float*)d_in[9];
    const float* conv_b = (const float*)d_in[10];
    const float* Wskip  = (const float*)d_in[11];
    const float* bskip  = (const float*)d_in[12];
    const float* Wi     = (const float*)d_in[13];
    const float* bi     = (const float*)d_in[14];
    const float* Wf     = (const float*)d_in[15];
    const float* bf_    = (const float*)d_in[16];
    const float* Wo     = (const float*)d_in[17];
    const float* bo     = (const float*)d_in[18];
    const float* Wq     = (const float*)d_in[19];
    const float* bq     = (const float*)d_in[20];
    const float* Wk     = (const float*)d_in[21];
    const float* bk     = (const float*)d_in[22];
    const float* Wv     = (const float*)d_in[23];
    const float* bv     = (const float*)d_in[24];
    const float* Wd     = (const float*)d_in[25];
    const float* bd     = (const float*)d_in[26];
    float* out = (float*)d_out;

    fp16 *xn16, *xt16, *xc16, *cm16;
    fp16 *WlrT, *WsT, *WqT, *WkT, *WvT, *WoT, *WdT;
    float *xt, *xc, *r, *skip, *q, *k, *v, *o, *gi, *gf, *aex, *Mex, *bias_lr;
    float *WiT, *WfT;
    cudaGetSymbolAddress((void**)&xn16, g_xn16);
    cudaGetSymbolAddress((void**)&xt,   g_xt);   cudaGetSymbolAddress((void**)&xt16, g_xt16);
    cudaGetSymbolAddress((void**)&xc,   g_xc);   cudaGetSymbolAddress((void**)&xc16, g_xc16);
    cudaGetSymbolAddress((void**)&r,    g_r);    cudaGetSymbolAddress((void**)&skip, g_skip);
    cudaGetSymbolAddress((void**)&q,    g_q);    cudaGetSymbolAddress((void**)&k,    g_k);
    cudaGetSymbolAddress((void**)&v,    g_v);    cudaGetSymbolAddress((void**)&o,    g_o);
    cudaGetSymbolAddress((void**)&gi,   g_ig);   cudaGetSymbolAddress((void**)&gf,   g_fg);
    cudaGetSymbolAddress((void**)&aex,  g_a);    cudaGetSymbolAddress((void**)&Mex,  g_M);
    cudaGetSymbolAddress((void**)&cm16, g_cm16);
    cudaGetSymbolAddress((void**)&WlrT, g_WlrT);
    cudaGetSymbolAddress((void**)&WsT,  g_WsT);  cudaGetSymbolAddress((void**)&WqT,  g_WqT);
    cudaGetSymbolAddress((void**)&WkT,  g_WkT);  cudaGetSymbolAddress((void**)&WvT,  g_WvT);
    cudaGetSymbolAddress((void**)&WoT,  g_WoT);  cudaGetSymbolAddress((void**)&WdT,  g_WdT);
    cudaGetSymbolAddress((void**)&bias_lr, g_bias_lr);
    cudaGetSymbolAddress((void**)&WiT,  g_WiT);  cudaGetSymbolAddress((void**)&WfT,  g_WfT);

    cudaFuncSetAttribute(gemm_mma_kernel,
                         cudaFuncAttributeMaxDynamicSharedMemorySize, GSMEM_BYTES);
    cudaFuncSetAttribute(attn_kernel,
                         cudaFuncAttributeMaxDynamicSharedMemorySize, ASM_BYTES);

    // 1. merged weight prep (8 transpose jobs in one launch)
    {
        PrepJobs pj{};
        const float* Ws[8] = { Wl, Wr, Wskip, Wq, Wk, Wv, Wo, Wd };
        fp16* Ts[8] = { WlrT, WlrT + (size_t)PP * DD, WsT, WqT, WkT, WvT, WoT, WdT };
        int Ks[8] = { DD, DD, PP, PP, PP, PP, PP, HD };
        int Ns[8] = { PP, HD, HD, HD, HD, HD, HD, DD };
        int cum = 0;
        for (int i = 0; i < 8; i++) {
            pj.W[i] = Ws[i]; pj.T[i] = Ts[i];
            pj.K[i] = Ks[i]; pj.N[i] = Ns[i];
            pj.cum[i] = cum;
            cum += (Ns[i] / 32) * (Ks[i] / 32);
        }
        pj.cum[8] = cum;
        prep_all_kernel<<<cum, 256>>>(pj);
    }
    misc_prep_kernel<<<74, 256>>>(bl, br, Wi, Wf);

    // 2. layernorm -> xn fp16
    ln_kernel<<<NTOK, 256>>>(x, ln_w, ln_b, xn16);

    // 3. merged [xt | r] = xn @ [Wl | Wr] + [bl | br]
    {
        GemmParams p{}; p.K = DD;
        p.jobs[0] = { xn16, WlrT, bias_lr, nullptr, xt, xt16, r, PP, PP, HD };
        gemm_mma_kernel<<<dim3(2560/128, NTOK/128, 1), 256, GSMEM_BYTES>>>(p);
    }
    // 4. conv + silu -> xc
    conv_silu_kernel<<<dim3(NTOK, PP/256), 256>>>(xt, conv_w, conv_b, xc, xc16);

    // 5. five P->HD projections in one batched launch
    {
        const int NC = 1 << 30;
        GemmParams p{}; p.K = PP;
        p.jobs[0] = { xc16, WsT, bskip, nullptr, skip, nullptr, nullptr, NC, HD, 0 };
        p.jobs[1] = { xc16, WqT, bq,    nullptr, q,    nullptr, nullptr, NC, HD, 0 };
        p.jobs[2] = { xc16, WkT, bk,    nullptr, k,    nullptr, nullptr, NC, HD, 0 };
        p.jobs[3] = { xt16, WvT, bv,    nullptr, v,    nullptr, nullptr, NC, HD, 0 };
        p.jobs[4] = { xt16, WoT, bo,    nullptr, o,    nullptr, nullptr, NC, HD, 0 };
        gemm_mma_kernel<<<dim3(HD/128, NTOK/128, 5), 256, GSMEM_BYTES>>>(p);
    }
    // 6. i/f gates (fp32, coalesced) + prefix scans
    gates_kernel<<<NTOK, 256>>>(xc, WiT, bi, WfT, bf_, gi, gf);
    gatescan_kernel<<<BB*HH, TT>>>(gi, gf, aex, Mex);

    // 7. parallel attention-form scan -> comb fp16
    attn_kernel<<<dim3(TT/QT, BB*HH), 256, ASM_BYTES>>>(
        q, k, v, aex, Mex, o, skip, r, hln_w, hln_b, cm16);

    // 8. out = comb @ Wd + bd + x
    {
        const int NC = 1 << 30;
        GemmParams p{}; p.K = HD;
        p.jobs[0] = { cm16, WdT, bd, x, out, nullptr, nullptr, NC, DD, 0 };
        gemm_mma_kernel<<<dim3(DD/128, NTOK/128, 1), 256, GSMEM_BYTES>>>(p);
    }
}

// round 15
// speedup vs baseline: 1.2355x; 1.0288x over previous
#include <cuda_runtime.h>
#include <cuda_fp16.h>
#include <cstdint>
#include <math.h>

typedef __half fp16;

// Problem constants
#define BB 4
#define TT 512
#define DD 1024
#define HH 8
#define DH 64
#define HD 512
#define PP 2048
#define NTOK (BB*TT)          // 2048 tokens

// ================= scratch (device globals) =================================
__device__ fp16  g_xn16[NTOK*DD];
__device__ float g_xt  [NTOK*PP];
__device__ fp16  g_xt16[NTOK*PP];
__device__ float g_xc  [NTOK*PP];
__device__ fp16  g_xc16[NTOK*PP];
__device__ float g_r   [NTOK*HD], g_skip[NTOK*HD];
__device__ float g_q   [NTOK*HD], g_k   [NTOK*HD];
__device__ float g_v   [NTOK*HD], g_o   [NTOK*HD];
__device__ float g_ig  [NTOK*HH], g_fg  [NTOK*HH];
__device__ float g_a   [BB*HH*TT], g_M [BB*HH*TT];
__device__ fp16  g_cm16[NTOK*HD];
// transposed weights (fp16): WT[N,K]
__device__ fp16 g_WlrT[2560*DD];      // [Wl | Wr] cols, K=1024
__device__ fp16 g_WsT[HD*PP], g_WqT[HD*PP], g_WkT[HD*PP];
__device__ fp16 g_WvT[HD*PP], g_WoT[HD*PP], g_WdT[DD*HD];
__device__ float g_bias_lr[2560];
__device__ float g_WiT[HH*PP], g_WfT[HH*PP];   // gate weights transposed [H][P]

__device__ __forceinline__ uint32_t smem_u32(const void* p) {
    uint32_t a;
    asm("{ .reg .u64 t; cvta.to.shared.u64 t, %1; cvt.u32.u64 %0, t; }"
        : "=r"(a) : "l"(p));
    return a;
}
__device__ __forceinline__ void cp16(uint32_t s, const void* g) {
    asm volatile("cp.async.cg.shared.global [%0], [%1], 16;" :: "r"(s), "l"(g));
}
__device__ __forceinline__ void ldm4(uint32_t addr, uint32_t* r) {
    asm volatile("ldmatrix.sync.aligned.m8n8.x4.shared.b16 {%0,%1,%2,%3}, [%4];"
                 : "=r"(r[0]), "=r"(r[1]), "=r"(r[2]), "=r"(r[3]) : "r"(addr));
}
__device__ __forceinline__ void mma16816(float* c, const uint32_t* a,
                                         uint32_t b0, uint32_t b1) {
    asm volatile("mma.sync.aligned.m16n8k16.row.col.f32.f16.f16.f32 "
        "{%0,%1,%2,%3}, {%4,%5,%6,%7}, {%8,%9}, {%0,%1,%2,%3};"
        : "+f"(c[0]), "+f"(c[1]), "+f"(c[2]), "+f"(c[3])
        : "r"(a[0]), "r"(a[1]), "r"(a[2]), "r"(a[3]), "r"(b0), "r"(b1));
}

// ============ fused preprocessing: 8 weight transposes + misc + LN =========
struct FusedPrep {
    const float* W[8];
    fp16* T[8];
    int K[8], N[8], cum[9];
    const float *bl, *br, *Wi, *Wf;
    const float *x, *lnw, *lnb;
    fp16* xn16;
    int miscEnd;                       // cum[8] + 74
};
__global__ __launch_bounds__(256) void fused_prep_kernel(FusedPrep fp)
{
    __shared__ float shmem[32 * 33];
    const int bx = blockIdx.x, tid = threadIdx.x;

    if (bx < fp.cum[8]) {
        // ---- weight transpose + fp16 convert
        int j = 0;
        #pragma unroll
        for (int i = 0; i < 8; i++) if (bx >= fp.cum[i + 1]) j = i + 1;
        const int local = bx - fp.cum[j];
        const int K = fp.K[j], N = fp.N[j];
        const int nbn = N / 32;
        const int n0 = (local % nbn) * 32, k0 = (local / nbn) * 32;
        const float* W = fp.W[j];
        fp16* T = fp.T[j];
        float (*tile)[33] = (float(*)[33])shmem;
        int tx = tid & 31, ty = tid >> 5;
        for (int r = ty; r < 32; r += 8)
            tile[r][tx] = W[(size_t)(k0 + r) * N + n0 + tx];
        __syncthreads();
        for (int r = ty; r < 32; r += 8)
            T[(size_t)(n0 + r) * K + k0 + tx] = __float2half(tile[tx][r]);
    } else if (bx < fp.miscEnd) {
        // ---- biases + gate weight transpose
        const int blk = bx - fp.cum[8];
        if (blk < 10) {
            int idx = blk * 256 + tid;
            if (idx < 2560)
                g_bias_lr[idx] = (idx < PP) ? fp.bl[idx] : fp.br[idx - PP];
        } else {
            int idx = (blk - 10) * 256 + tid;   // 0..16383 over [8][2048]
            int h = idx >> 11, p = idx & 2047;
            g_WiT[idx] = fp.Wi[p * HH + h];
            g_WfT[idx] = fp.Wf[p * HH + h];
        }
    } else {
        // ---- layernorm -> fp16
        const int t = bx - fp.miscEnd;
        const float* row = fp.x + (size_t)t * DD;
        float s = 0.f, s2 = 0.f;
        for (int i = tid; i < DD; i += 256) {
            float v = row[i]; s += v; s2 += v * v;
        }
        int warp = tid >> 5, lane = tid & 31;
        #pragma unroll
        for (int o = 16; o; o >>= 1) {
            s  += __shfl_xor_sync(0xffffffffu, s,  o);
            s2 += __shfl_xor_sync(0xffffffffu, s2, o);
        }
        if (lane == 0) { shmem[warp] = s; shmem[8 + warp] = s2; }
        __syncthreads();
        if (tid == 0) {
            float ts = 0.f, ts2 = 0.f;
            #pragma unroll
            for (int i = 0; i < 8; i++) { ts += shmem[i]; ts2 += shmem[8 + i]; }
            float mu  = ts  * (1.f / DD);
            float var = ts2 * (1.f / DD) - mu * mu;
            shmem[0] = mu; shmem[1] = rsqrtf(var + 1e-6f);
        }
        __syncthreads();
        float mu = shmem[0], rstd = shmem[1];
        for (int i = tid; i < DD; i += 256)
            fp.xn16[(size_t)t * DD + i] =
                __float2half((row[i] - mu) * rstd * fp.lnw[i] + fp.lnb[i]);
    }
}

// ============ mma.sync fp16 single-pass GEMM (BK=32, 4-stage) ==============
struct GemmJob {
    const fp16 *A, *B;
    const float *bias, *res;
    float *out;
    fp16 *o16;
    float *out2;                  // columns >= ncut go here (ld = ldo2)
    int ncut, ldo, ldo2;
};
struct GemmParams { GemmJob jobs[5]; int K; };

#define PADK 40                        // halves per smem row (32 + 8 pad)
#define OPT  (128*PADK)                // halves per operand tile
#define STG2 (2*OPT)                   // halves per stage (A, B)
#define NSTG 4
#define GSMEM_BYTES (NSTG*STG2*2)      // 81920 B -> 2 CTAs/SM

__global__ __launch_bounds__(256, 2) void gemm_mma_kernel(GemmParams p)
{
    const GemmJob J = p.jobs[blockIdx.z];
    const int bm = blockIdx.y * 128, bn = blockIdx.x * 128;

    extern __shared__ fp16 smg[];
    const uint32_t sbase = smem_u32(smg);
    const int K = p.K;
    const int tid = threadIdx.x, lane = tid & 31, wid = tid >> 5;
    const int warpM = wid & 3, warpN = wid >> 2;    // 4 x 2 warps, tile 32x64

    const fp16* gsrc[2];
    gsrc[0] = J.A + (size_t)bm * K;
    gsrc[1] = J.B + (size_t)bn * K;

    const int lrow = tid >> 1;
    const int lcol = (tid & 1) * 16;   // halves
    const uint32_t swr = sbase + (uint32_t)(lrow * PADK + lcol) * 2;

    float acc[2][8][4];
    #pragma unroll
    for (int i = 0; i < 2; i++)
        #pragma unroll
        for (int j = 0; j < 8; j++)
            #pragma unroll
            for (int e = 0; e < 4; e++) acc[i][j][e] = 0.f;

    const int NT = K / 32;

    // preload stages 0..2
    #pragma unroll
    for (int s = 0; s < 3; s++) {
        #pragma unroll
        for (int w = 0; w < 2; w++) {
            const fp16* g = gsrc[w] + (size_t)lrow * K + s * 32 + lcol;
            uint32_t sa = swr + (uint32_t)(s * STG2 + w * OPT) * 2;
            cp16(sa, g); cp16(sa + 16, g + 8);
        }
        asm volatile("cp.async.commit_group;");
    }

    for (int kt = 0; kt < NT; kt++) {
        if (kt < NT - 2)      asm volatile("cp.async.wait_group 2;");
        else if (kt < NT - 1) asm volatile("cp.async.wait_group 1;");
        else                  asm volatile("cp.async.wait_group 0;");
        __syncthreads();

        // prefetch kt+3 (overlaps with compute below)
        if (kt + 3 < NT) {
            const int s = (kt + 3) % NSTG;
            const int k0 = (kt + 3) * 32;
            #pragma unroll
            for (int w = 0; w < 2; w++) {
                const fp16* g = gsrc[w] + (size_t)lrow * K + k0 + lcol;
                uint32_t sa = swr + (uint32_t)(s * STG2 + w * OPT) * 2;
                cp16(sa, g); cp16(sa + 16, g + 8);
            }
            asm volatile("cp.async.commit_group;");
        }

        const uint32_t stg = sbase + (uint32_t)((kt % NSTG) * STG2) * 2;
        #pragma unroll
        for (int ks = 0; ks < 2; ks++) {
            const int koff = ks * 16 + ((lane >> 4) << 3);
            const int rsel = lane & 15;
            uint32_t a[2][4], b[4][4];
            #pragma unroll
            for (int i = 0; i < 2; i++) {
                const int row = warpM * 32 + i * 16 + rsel;
                ldm4(stg + (uint32_t)(row * PADK + koff) * 2, a[i]);
            }
            #pragma unroll
            for (int j = 0; j < 4; j++) {
                const int row = warpN * 64 + j * 16 + rsel;
                ldm4(stg + (uint32_t)(OPT + row * PADK + koff) * 2, b[j]);
            }
            #pragma unroll
            for (int i = 0; i < 2; i++)
                #pragma unroll
                for (int j = 0; j < 8; j++)
                    mma16816(acc[i][j], a[i],
                             b[j >> 1][j & 1], b[j >> 1][(j & 1) + 2]);
        }
    }

    const int er = (lane >> 2);
    const int ec = (lane & 3) * 2;
    #pragma unroll
    for (int i = 0; i < 2; i++) {
        #pragma unroll
        for (int j = 0; j < 8; j++) {
            const int row0 = bm + warpM * 32 + i * 16 + er;
            const int col0 = bn + warpN * 64 + j * 8 + ec;
            #pragma unroll
            for (int e = 0; e < 4; e++) {
                const int row = row0 + (e >> 1) * 8;
                const int col = col0 + (e & 1);
                float v = acc[i][j][e] + J.bias[col];
                if (col >= J.ncut) {
                    J.out2[(size_t)row * J.ldo2 + (col - J.ncut)] = v;
                } else {
                    if (J.res) v += J.res[(size_t)row * J.ldo + col];
                    const size_t idx = (size_t)row * J.ldo + col;
                    J.out[idx] = v;
                    if (J.o16) J.o16[idx] = __float2half(v);
                }
            }
        }
    }
}

// ============== causal feature-conv + silu (float4, zero-padded) ===========
__global__ __launch_bounds__(256) void conv_silu_kernel(
    const float* __restrict__ xt, const float* __restrict__ cw,
    const float* __restrict__ cbp, float* __restrict__ xc,
    fp16* __restrict__ xc16)
{
    const int fi = blockIdx.x * 256 + threadIdx.x;     // float4 index
    const int col4 = fi & (PP / 4 - 1);                // position within row
    const float4* src = (const float4*)xt;
    const float4 cur = src[fi];
    float4 prev = make_float4(0.f, 0.f, 0.f, 0.f);
    if (col4 != 0) prev = src[fi - 1];
    const float w0 = cw[0], w1 = cw[1], w2 = cw[2], w3 = cw[3], cb = cbp[0];
    // buf = [p-3, p-2, p-1, p, p+1, p+2, p+3] for p = 4*col4
    const float buf[7] = { prev.y, prev.z, prev.w, cur.x, cur.y, cur.z, cur.w };
    float o[4];
    #pragma unroll
    for (int e = 0; e < 4; e++) {
        float acc = w0*buf[e] + w1*buf[e+1] + w2*buf[e+2] + w3*buf[e+3] + cb;
        o[e] = acc / (1.f + __expf(-acc));
    }
    ((float4*)xc)[fi] = make_float4(o[0], o[1], o[2], o[3]);
    __half2* h2 = (__half2*)(xc16 + (size_t)fi * 4);
    h2[0] = __floats2half2_rn(o[0], o[1]);
    h2[1] = __floats2half2_rn(o[2], o[3]);
}

// ================= i/f gates (fp32, coalesced transposed weights) ==========
__global__ __launch_bounds__(256) void gates_kernel(
    const float* __restrict__ xc,
    const float* __restrict__ WiT, const float* __restrict__ bi,
    const float* __restrict__ WfT, const float* __restrict__ bf_,
    float* __restrict__ gi, float* __restrict__ gf)
{
    int t = blockIdx.x;
    int warp = threadIdx.x >> 5, lane = threadIdx.x & 31;
    const float* row = xc + (size_t)t * PP;
    const float* wi = WiT + warp * PP;
    const float* wf = WfT + warp * PP;
    float si = 0.f, sf = 0.f;
    for (int p = lane * 4; p < PP; p += 128) {
        float4 xv = *(const float4*)(row + p);
        float4 a  = *(const float4*)(wi + p);
        float4 b  = *(const float4*)(wf + p);
        si += xv.x*a.x + xv.y*a.y + xv.z*a.z + xv.w*a.w;
        sf += xv.x*b.x + xv.y*b.y + xv.z*b.z + xv.w*b.w;
    }
    #pragma unroll
    for (int o = 16; o; o >>= 1) {
        si += __shfl_xor_sync(0xffffffffu, si, o);
        sf += __shfl_xor_sync(0xffffffffu, sf, o);
    }
    if (lane == 0) {
        float a  = si + bi[warp];
        float b2 = sf + bf_[warp];
        gi[t * HH + warp] = 15.f * tanhf(a  * (1.f / 15.f));
        gf[t * HH + warp] = 15.f * tanhf(b2 * (1.f / 15.f));
    }
}

// ================= gate prefix scans (exact linearization) =================
__global__ __launch_bounds__(TT) void gatescan_kernel(
    const float* __restrict__ gi, const float* __restrict__ gf,
    float* __restrict__ a_out, float* __restrict__ M_out)
{
    const int bh = blockIdx.x;          // b*HH + h
    const int b = bh >> 3, h = bh & 7;
    const int t = threadIdx.x;
    __shared__ float sf[TT], sa[TT];
    const int gidx = (b * TT + t) * HH + h;
    sf[t] = gf[gidx];
    const float iv = gi[gidx];
    __syncthreads();
    #pragma unroll
    for (int st = 1; st < TT; st <<= 1) {
        float add = (t >= st) ? sf[t - st] : 0.f;
        __syncthreads();
        sf[t] += add;
        __syncthreads();
    }
    const float a = iv - sf[t];
    a_out[bh * TT + t] = a;
    sa[t] = a;
    __syncthreads();
    #pragma unroll
    for (int st = 1; st < TT; st <<= 1) {
        float mx = (t >= st) ? sa[t - st] : -3.4e38f;
        __syncthreads();
        sa[t] = fmaxf(sa[t], mx);
        __syncthreads();
    }
    M_out[bh * TT + t] = fmaxf(0.f, sa[t]);
}

// ================= parallel attention-form scan ============================
#define QT 64
#define AP 68                       // row pad (floats); 272B, 16B aligned
#define ASM_BYTES ((4*QT*AP + QT) * 4)

__global__ __launch_bounds__(256) void attn_kernel(
    const float* __restrict__ q, const float* __restrict__ kraw,
    const float* __restrict__ v, const float* __restrict__ aex,
    const float* __restrict__ Mex, const float* __restrict__ oraw,
    const float* __restrict__ skip, const float* __restrict__ rraw,
    const float* __restrict__ hlnw, const float* __restrict__ hlnb,
    fp16* __restrict__ out16)
{
    const int bh = blockIdx.y, b = bh >> 3, h = bh & 7;
    const int t0 = blockIdx.x * QT;
    extern __shared__ float sm[];
    float* ks = sm;                  // [64][AP]
    float* vs = ks + QT * AP;
    float* qs = vs + QT * AP;
    float* ss = qs + QT * AP;
    float* as_ = ss + QT * AP;       // [64]

    const int tid = threadIdx.x;
    const int qi = tid >> 2, sub = tid & 3;
    const int tq = t0 + qi;
    const size_t qbase = (size_t)(b * TT + tq) * HD + h * DH;

    {
        const int lr = tid >> 2, lc = (tid & 3) * 16;
        const float* src = q + (size_t)(b * TT + t0 + lr) * HD + h * DH + lc;
        #pragma unroll
        for (int i = 0; i < 16; i += 4)
            *(float4*)&qs[lr * AP + lc + i] = *(const float4*)(src + i);
    }
    __syncthreads();

    const float Mt = Mex[bh * TT + tq];
    float num[16];
    #pragma unroll
    for (int i = 0; i < 16; i++) num[i] = 0.f;
    float den = 0.f;

    for (int j0 = 0; j0 <= t0; j0 += QT) {
        {
            const int lr = tid >> 2, lc = (tid & 3) * 16;
            const size_t gb = (size_t)(b * TT + j0 + lr) * HD + h * DH + lc;
            #pragma unroll
            for (int i = 0; i < 16; i += 4) {
                *(float4*)&ks[lr * AP + lc + i] = *(const float4*)(kraw + gb + i);
                *(float4*)&vs[lr * AP + lc + i] = *(const float4*)(v + gb + i);
            }
            if (tid < QT) as_[tid] = aex[bh * TT + j0 + tid];
        }
        __syncthreads();

        float sc[16];
        #pragma unroll
        for (int jj = 0; jj < 16; jj++) sc[jj] = 0.f;
        const float* qrow = &qs[qi * AP];
        #pragma unroll 4
        for (int d = 0; d < DH; d += 4) {
            float q0 = qrow[d], q1 = qrow[d+1], q2 = qrow[d+2], q3 = qrow[d+3];
            #pragma unroll
            for (int jj = 0; jj < 16; jj++) {
                const float* kr = &ks[(sub + 4*jj) * AP + d];
                sc[jj] += q0*kr[0] + q1*kr[1] + q2*kr[2] + q3*kr[3];
            }
        }
        const bool diag = (j0 == t0);
        #pragma unroll
        for (int jj = 0; jj < 16; jj++) {
            const int j = sub + 4*jj;
            float w = (diag && j > qi) ? 0.f
                      : __expf(as_[j] - Mt) * 0.125f * sc[jj];
            ss[qi * AP + j] = w;
            den += w;
        }
        __syncthreads();

        #pragma unroll 8
        for (int j = 0; j < QT; j++) {
            const float s = ss[qi * AP + j];
            const float* vr = &vs[j * AP + sub];
            #pragma unroll
            for (int dd = 0; dd < 16; dd++)
                num[dd] += s * vr[4*dd];
        }
        __syncthreads();
    }

    float sumq = 0.f;
    #pragma unroll
    for (int dd = 0; dd < 16; dd++) sumq += qs[qi * AP + sub + 4*dd];
    den  += __shfl_xor_sync(0xffffffffu, den, 1);
    den  += __shfl_xor_sync(0xffffffffu, den, 2);
    sumq += __shfl_xor_sync(0xffffffffu, sumq, 1);
    sumq += __shfl_xor_sync(0xffffffffu, sumq, 2);
    den = fmaxf(den + __expf(-Mt) * sumq, 1.0f);
    const float rden = 1.f / den;

    float hh[16], s1 = 0.f, s2 = 0.f;
    #pragma unroll
    for (int dd = 0; dd < 16; dd++) {
        const int d = sub + 4*dd;
        const float ov = oraw[qbase + d];
        const float og = 1.f / (1.f + __expf(-ov));
        const float hv = og * num[dd] * rden;
        hh[dd] = hv;
        s1 += hv; s2 += hv * hv;
    }
    s1 += __shfl_xor_sync(0xffffffffu, s1, 1);
    s1 += __shfl_xor_sync(0xffffffffu, s1, 2);
    s2 += __shfl_xor_sync(0xffffffffu, s2, 1);
    s2 += __shfl_xor_sync(0xffffffffu, s2, 2);
    const float mu  = s1 * (1.f / DH);
    const float var = s2 * (1.f / DH) - mu * mu;
    const float rstd = rsqrtf(var + 1e-6f);
    #pragma unroll
    for (int dd = 0; dd < 16; dd++) {
        const int d = sub + 4*dd;
        const float hn = (hh[dd] - mu) * rstd * hlnw[h*DH + d] + hlnb[h*DH + d];
        const float rv = rraw[qbase + d];
        const float sil = rv / (1.f + __expf(-rv));
        out16[qbase + d] = __float2half((hn + skip[qbase + d]) * sil);
    }
}

// ===========================================================================
extern "C" void kernel_launch(void* const* d_in, const int* in_sizes, int n_in,
                              void* d_out, int out_size)
{
    const float* x      = (const float*)d_in[0];
    const float* ln_w   = (const float*)d_in[1];
    const float* ln_b   = (const float*)d_in[2];
    const float* hln_w  = (const float*)d_in[3];
    const float* hln_b  = (const float*)d_in[4];
    const float* Wl     = (const float*)d_in[5];
    const float* bl     = (const float*)d_in[6];
    const float* Wr     = (const float*)d_in[7];
    const float* br     = (const float*)d_in[8];
    const float* conv_w = (const float*)d_in[9];
    const float* conv_b = (const float*)d_in[10];
    const float* Wskip  = (const float*)d_in[11];
    const float* bskip  = (const float*)d_in[12];
    const float* Wi     = (const float*)d_in[13];
    const float* bi     = (const float*)d_in[14];
    const float* Wf     = (const float*)d_in[15];
    const float* bf_    = (const float*)d_in[16];
    const float* Wo     = (const float*)d_in[17];
    const float* bo     = (const float*)d_in[18];
    const float* Wq     = (const float*)d_in[19];
    const float* bq     = (const float*)d_in[20];
    const float* Wk     = (const float*)d_in[21];
    const float* bk     = (const float*)d_in[22];
    const float* Wv     = (const float*)d_in[23];
    const float* bv     = (const float*)d_in[24];
    const float* Wd     = (const float*)d_in[25];
    const float* bd     = (const float*)d_in[26];
    float* out = (float*)d_out;

    fp16 *xn16, *xt16, *xc16, *cm16;
    fp16 *WlrT, *WsT, *WqT, *WkT, *WvT, *WoT, *WdT;
    float *xt, *xc, *r, *skip, *q, *k, *v, *o, *gi, *gf, *aex, *Mex, *bias_lr;
    float *WiT, *WfT;
    cudaGetSymbolAddress((void**)&xn16, g_xn16);
    cudaGetSymbolAddress((void**)&xt,   g_xt);   cudaGetSymbolAddress((void**)&xt16, g_xt16);
    cudaGetSymbolAddress((void**)&xc,   g_xc);   cudaGetSymbolAddress((void**)&xc16, g_xc16);
    cudaGetSymbolAddress((void**)&r,    g_r);    cudaGetSymbolAddress((void**)&skip, g_skip);
    cudaGetSymbolAddress((void**)&q,    g_q);    cudaGetSymbolAddress((void**)&k,    g_k);
    cudaGetSymbolAddress((void**)&v,    g_v);    cudaGetSymbolAddress((void**)&o,    g_o);
    cudaGetSymbolAddress((void**)&gi,   g_ig);   cudaGetSymbolAddress((void**)&gf,   g_fg);
    cudaGetSymbolAddress((void**)&aex,  g_a);    cudaGetSymbolAddress((void**)&Mex,  g_M);
    cudaGetSymbolAddress((void**)&cm16, g_cm16);
    cudaGetSymbolAddress((void**)&WlrT, g_WlrT);
    cudaGetSymbolAddress((void**)&WsT,  g_WsT);  cudaGetSymbolAddress((void**)&WqT,  g_WqT);
    cudaGetSymbolAddress((void**)&WkT,  g_WkT);  cudaGetSymbolAddress((void**)&WvT,  g_WvT);
    cudaGetSymbolAddress((void**)&WoT,  g_WoT);  cudaGetSymbolAddress((void**)&WdT,  g_WdT);
    cudaGetSymbolAddress((void**)&bias_lr, g_bias_lr);
    cudaGetSymbolAddress((void**)&WiT,  g_WiT);  cudaGetSymbolAddress((void**)&WfT,  g_WfT);

    cudaFuncSetAttribute(gemm_mma_kernel,
                         cudaFuncAttributeMaxDynamicSharedMemorySize, GSMEM_BYTES);
    cudaFuncSetAttribute(attn_kernel,
                         cudaFuncAttributeMaxDynamicSharedMemorySize, ASM_BYTES);

    // 1. fused preprocessing: weight transposes + biases/gate-weights + LN
    {
        FusedPrep fp{};
        const float* Ws[8] = { Wl, Wr, Wskip, Wq, Wk, Wv, Wo, Wd };
        fp16* Ts[8] = { WlrT, WlrT + (size_t)PP * DD, WsT, WqT, WkT, WvT, WoT, WdT };
        int Ks[8] = { DD, DD, PP, PP, PP, PP, PP, HD };
        int Ns[8] = { PP, HD, HD, HD, HD, HD, HD, DD };
        int cum = 0;
        for (int i = 0; i < 8; i++) {
            fp.W[i] = Ws[i]; fp.T[i] = Ts[i];
            fp.K[i] = Ks[i]; fp.N[i] = Ns[i];
            fp.cum[i] = cum;
            cum += (Ns[i] / 32) * (Ks[i] / 32);
        }
        fp.cum[8] = cum;
        fp.bl = bl; fp.br = br; fp.Wi = Wi; fp.Wf = Wf;
        fp.x = x; fp.lnw = ln_w; fp.lnb = ln_b; fp.xn16 = xn16;
        fp.miscEnd = cum + 74;
        fused_prep_kernel<<<cum + 74 + NTOK, 256>>>(fp);
    }

    // 2. merged [xt | r] = xn @ [Wl | Wr] + [bl | br]
    {
        GemmParams p{}; p.K = DD;
        p.jobs[0] = { xn16, WlrT, bias_lr, nullptr, xt, xt16, r, PP, PP, HD };
        gemm_mma_kernel<<<dim3(2560/128, NTOK/128, 1), 256, GSMEM_BYTES>>>(p);
    }
    // 3. conv + silu -> xc (float4, causal zero-pad)
    conv_silu_kernel<<<NTOK * PP / 4 / 256, 256>>>(xt, conv_w, conv_b, xc, xc16);

    // 4. five P->HD projections in one batched launch
    {
        const int NC = 1 << 30;
        GemmParams p{}; p.K = PP;
        p.jobs[0] = { xc16, WsT, bskip, nullptr, skip, nullptr, nullptr, NC, HD, 0 };
        p.jobs[1] = { xc16, WqT, bq,    nullptr, q,    nullptr, nullptr, NC, HD, 0 };
        p.jobs[2] = { xc16, WkT, bk,    nullptr, k,    nullptr, nullptr, NC, HD, 0 };
        p.jobs[3] = { xt16, WvT, bv,    nullptr, v,    nullptr, nullptr, NC, HD, 0 };
        p.jobs[4] = { xt16, WoT, bo,    nullptr, o,    nullptr, nullptr, NC, HD, 0 };
        gemm_mma_kernel<<<dim3(HD/128, NTOK/128, 5), 256, GSMEM_BYTES>>>(p);
    }
    // 5. i/f gates (fp32, coalesced) + prefix scans
    gates_kernel<<<NTOK, 256>>>(xc, WiT, bi, WfT, bf_, gi, gf);
    gatescan_kernel<<<BB*HH, TT>>>(gi, gf, aex, Mex);

    // 6. parallel attention-form scan -> comb fp16
    attn_kernel<<<dim3(TT/QT, BB*HH), 256, ASM_BYTES>>>(
        q, k, v, aex, Mex, o, skip, r, hln_w, hln_b, cm16);

    // 7. out = comb @ Wd + bd + x
    {
        const int NC = 1 << 30;
        GemmParams p{}; p.K = HD;
        p.jobs[0] = { cm16, WdT, bd, x, out, nullptr, nullptr, NC, DD, 0 };
        gemm_mma_kernel<<<dim3(DD/128, NTOK/128, 1), 256, GSMEM_BYTES>>>(p);
    }
}